// round 3
// baseline (speedup 1.0000x reference)
#include <cuda_runtime.h>

#define BT 2048
#define NF 128
#define CC 256
#define DD 128

// Precomputed fused weight Wc = Wg @ Wv and bias bc = Wg @ bv + bg
__device__ float g_Wc[CC * CC];
__device__ float g_bc[CC];

__global__ void prep_kernel(const float* __restrict__ Wg, const float* __restrict__ Wv,
                            const float* __restrict__ bv, const float* __restrict__ bg)
{
    __shared__ float sWg[CC];
    __shared__ float sred[256];
    const int i = blockIdx.x;
    const int j = threadIdx.x;
    const float wg = Wg[i * CC + j];
    sWg[j] = wg;
    __syncthreads();
    float acc = 0.f;
#pragma unroll 8
    for (int k = 0; k < CC; ++k) acc = fmaf(sWg[k], Wv[k * CC + j], acc);
    g_Wc[i * CC + j] = acc;
    sred[j] = wg * bv[j];
    __syncthreads();
    for (int s = 128; s > 0; s >>= 1) {
        if (j < s) sred[j] += sred[j + s];
        __syncthreads();
    }
    if (j == 0) g_bc[i] = sred[0] + bg[i];
}

// Shared memory layout (floats)
constexpr int OFF_A   = 0;      // sQ [128][132], later attn [128][132]
constexpr int OFF_AX  = 16896;  // sKt [128][132] (phases 1-2), then ax [128][260]
constexpr int OFF_BT  = 50176;  // sBt staging [16][260]
constexpr int OFF_SA  = 54336;  // sA  staging [128][16]
constexpr int SMEM_FLOATS = 56384;   // 225536 bytes

__global__ void __launch_bounds__(256, 1)
fused_kernel(const float* __restrict__ x, const float* __restrict__ ee,
             const float* __restrict__ adj, const float* __restrict__ alpha_p,
             const float* __restrict__ Wq, const float* __restrict__ bq,
             const float* __restrict__ Wk, const float* __restrict__ bk,
             const float* __restrict__ gamma, const float* __restrict__ beta,
             float* __restrict__ out)
{
    extern __shared__ float sm[];
    float* sQ  = sm + OFF_A;    // stride 132 (also attn later)
    float* sKt = sm + OFF_AX;   // stride 132 (K transposed: [d][m])
    float* sAX = sm + OFF_AX;   // stride 260 (attn @ x, phases 3-4)
    float* sBt = sm + OFF_BT;   // stride 260
    float* sA  = sm + OFF_SA;   // stride 16

    const int tid = threadIdx.x;
    const int tm = tid >> 4;          // 0..15 (row group)
    const int tn = tid & 15;          // 0..15 (col group)
    const int rm = tm << 3;           // first of 8 rows owned by this thread
    const int b = blockIdx.x;
    const float* xb = x + (size_t)b * (NF * CC);

    float acc[8][16];

    // ================= Phase 1: [Q | K] = (x + ee) @ [Wq; Wk]^T + bias ============
#pragma unroll
    for (int i = 0; i < 8; i++)
#pragma unroll
        for (int j = 0; j < 16; j++) acc[i][j] = 0.f;

    for (int kt = 0; kt < CC; kt += 16) {
        { // stage xe tile: sA[r][kk] = x[b][r][kt+kk] + ee[r][kt+kk]
            const int r = tid >> 1;
            const int h = (tid & 1) << 3;
            const float* px = xb + r * CC + kt + h;
            const float* pe = ee + r * CC + kt + h;
            float4 v0 = *(const float4*)px;
            float4 v1 = *(const float4*)(px + 4);
            float4 e0 = *(const float4*)pe;
            float4 e1 = *(const float4*)(pe + 4);
            float* d = sA + r * 16 + h;
            d[0] = v0.x + e0.x; d[1] = v0.y + e0.y; d[2] = v0.z + e0.z; d[3] = v0.w + e0.w;
            d[4] = v1.x + e1.x; d[5] = v1.y + e1.y; d[6] = v1.z + e1.z; d[7] = v1.w + e1.w;
        }
        { // stage weight tile transposed: sBt[kk][n] = W[n][kt+kk], n = tid
            const float* wp = (tid < DD) ? (Wq + tid * CC + kt) : (Wk + (tid - DD) * CC + kt);
            float4 w0 = *(const float4*)wp;
            float4 w1 = *(const float4*)(wp + 4);
            float4 w2 = *(const float4*)(wp + 8);
            float4 w3 = *(const float4*)(wp + 12);
            float wv[16] = {w0.x, w0.y, w0.z, w0.w, w1.x, w1.y, w1.z, w1.w,
                            w2.x, w2.y, w2.z, w2.w, w3.x, w3.y, w3.z, w3.w};
#pragma unroll
            for (int kk = 0; kk < 16; kk++) sBt[kk * 260 + tid] = wv[kk];
        }
        __syncthreads();
#pragma unroll 4
        for (int kk = 0; kk < 16; kk++) {
            float a[8];
#pragma unroll
            for (int i = 0; i < 8; i++) a[i] = sA[(rm + i) * 16 + kk];
            float4 bb[4];
#pragma unroll
            for (int q = 0; q < 4; q++) bb[q] = *(const float4*)&sBt[kk * 260 + tn * 4 + q * 64];
#pragma unroll
            for (int i = 0; i < 8; i++) {
#pragma unroll
                for (int q = 0; q < 4; q++) {
                    acc[i][q * 4 + 0] = fmaf(a[i], bb[q].x, acc[i][q * 4 + 0]);
                    acc[i][q * 4 + 1] = fmaf(a[i], bb[q].y, acc[i][q * 4 + 1]);
                    acc[i][q * 4 + 2] = fmaf(a[i], bb[q].z, acc[i][q * 4 + 2]);
                    acc[i][q * 4 + 3] = fmaf(a[i], bb[q].w, acc[i][q * 4 + 3]);
                }
            }
        }
        __syncthreads();
    }
    // epilogue: Q rows -> sQ ; K rows transposed -> sKt[d][m]
#pragma unroll
    for (int q = 0; q < 4; q++) {
        const int n0 = tn * 4 + q * 64;
        if (q < 2) {
            float4 bias = *(const float4*)&bq[n0];
#pragma unroll
            for (int i = 0; i < 8; i++) {
                float4 v;
                v.x = acc[i][q * 4 + 0] + bias.x;
                v.y = acc[i][q * 4 + 1] + bias.y;
                v.z = acc[i][q * 4 + 2] + bias.z;
                v.w = acc[i][q * 4 + 3] + bias.w;
                *(float4*)&sQ[(rm + i) * 132 + n0] = v;
            }
        } else {
            const int nk = n0 - 128;
            float4 bias = *(const float4*)&bk[nk];
#pragma unroll
            for (int i = 0; i < 8; i++) {
                sKt[(nk + 0) * 132 + rm + i] = acc[i][q * 4 + 0] + bias.x;
                sKt[(nk + 1) * 132 + rm + i] = acc[i][q * 4 + 1] + bias.y;
                sKt[(nk + 2) * 132 + rm + i] = acc[i][q * 4 + 2] + bias.z;
                sKt[(nk + 3) * 132 + rm + i] = acc[i][q * 4 + 3] + bias.w;
            }
        }
    }
    __syncthreads();

    // ================= Phase 2: scores = Q K^T / sqrt(128) + fa*relu(adj); softmax =====
    float sc[8][8];
#pragma unroll
    for (int i = 0; i < 8; i++)
#pragma unroll
        for (int j = 0; j < 8; j++) sc[i][j] = 0.f;

#pragma unroll 4
    for (int d = 0; d < DD; d++) {
        float a[8];
#pragma unroll
        for (int i = 0; i < 8; i++) a[i] = sQ[(rm + i) * 132 + d];
        float4 b0 = *(const float4*)&sKt[d * 132 + tn * 4];
        float4 b1 = *(const float4*)&sKt[d * 132 + tn * 4 + 64];
#pragma unroll
        for (int i = 0; i < 8; i++) {
            sc[i][0] = fmaf(a[i], b0.x, sc[i][0]);
            sc[i][1] = fmaf(a[i], b0.y, sc[i][1]);
            sc[i][2] = fmaf(a[i], b0.z, sc[i][2]);
            sc[i][3] = fmaf(a[i], b0.w, sc[i][3]);
            sc[i][4] = fmaf(a[i], b1.x, sc[i][4]);
            sc[i][5] = fmaf(a[i], b1.y, sc[i][5]);
            sc[i][6] = fmaf(a[i], b1.z, sc[i][6]);
            sc[i][7] = fmaf(a[i], b1.w, sc[i][7]);
        }
    }
    const float fa = __ldg(alpha_p);
    const float invscale = 0.08838834764831845f;  // 1/sqrt(128)
#pragma unroll
    for (int i = 0; i < 8; i++) {
        const int gi = rm + i;
        float4 a0 = __ldg((const float4*)&adj[gi * DD + tn * 4]);
        float4 a1 = __ldg((const float4*)&adj[gi * DD + tn * 4 + 64]);
        sc[i][0] = sc[i][0] * invscale + fa * fmaxf(a0.x, 0.f);
        sc[i][1] = sc[i][1] * invscale + fa * fmaxf(a0.y, 0.f);
        sc[i][2] = sc[i][2] * invscale + fa * fmaxf(a0.z, 0.f);
        sc[i][3] = sc[i][3] * invscale + fa * fmaxf(a0.w, 0.f);
        sc[i][4] = sc[i][4] * invscale + fa * fmaxf(a1.x, 0.f);
        sc[i][5] = sc[i][5] * invscale + fa * fmaxf(a1.y, 0.f);
        sc[i][6] = sc[i][6] * invscale + fa * fmaxf(a1.z, 0.f);
        sc[i][7] = sc[i][7] * invscale + fa * fmaxf(a1.w, 0.f);
        float mx = sc[i][0];
#pragma unroll
        for (int j = 1; j < 8; j++) mx = fmaxf(mx, sc[i][j]);
#pragma unroll
        for (int off = 8; off; off >>= 1) mx = fmaxf(mx, __shfl_xor_sync(0xffffffffu, mx, off));
        float s = 0.f;
#pragma unroll
        for (int j = 0; j < 8; j++) { sc[i][j] = __expf(sc[i][j] - mx); s += sc[i][j]; }
#pragma unroll
        for (int off = 8; off; off >>= 1) s += __shfl_xor_sync(0xffffffffu, s, off);
        const float inv = 1.f / s;
#pragma unroll
        for (int j = 0; j < 8; j++) sc[i][j] *= inv;
    }
    __syncthreads();   // everyone done reading sQ/sKt
#pragma unroll
    for (int i = 0; i < 8; i++) {  // attn overwrites sQ region
        *(float4*)&sQ[(rm + i) * 132 + tn * 4]      = make_float4(sc[i][0], sc[i][1], sc[i][2], sc[i][3]);
        *(float4*)&sQ[(rm + i) * 132 + tn * 4 + 64] = make_float4(sc[i][4], sc[i][5], sc[i][6], sc[i][7]);
    }
    __syncthreads();

    // ================= Phase 3: ax = attn @ x[b]  (128x256, K=128) ==================
#pragma unroll
    for (int i = 0; i < 8; i++)
#pragma unroll
        for (int j = 0; j < 16; j++) acc[i][j] = 0.f;

    for (int kt = 0; kt < DD; kt += 16) {
        { // stage x rows: sBt[kk][n] = x[b][kt+kk][n]
            const int kk = tid >> 4;
            const int n0 = (tid & 15) << 4;
            const float* px = xb + (kt + kk) * CC + n0;
            float4 v0 = *(const float4*)px;
            float4 v1 = *(const float4*)(px + 4);
            float4 v2 = *(const float4*)(px + 8);
            float4 v3 = *(const float4*)(px + 12);
            float* d = &sBt[kk * 260 + n0];
            *(float4*)(d)      = v0;
            *(float4*)(d + 4)  = v1;
            *(float4*)(d + 8)  = v2;
            *(float4*)(d + 12) = v3;
        }
        __syncthreads();
#pragma unroll 4
        for (int kk = 0; kk < 16; kk++) {
            float a[8];
#pragma unroll
            for (int i = 0; i < 8; i++) a[i] = sQ[(rm + i) * 132 + kt + kk];  // attn
            float4 bb[4];
#pragma unroll
            for (int q = 0; q < 4; q++) bb[q] = *(const float4*)&sBt[kk * 260 + tn * 4 + q * 64];
#pragma unroll
            for (int i = 0; i < 8; i++) {
#pragma unroll
                for (int q = 0; q < 4; q++) {
                    acc[i][q * 4 + 0] = fmaf(a[i], bb[q].x, acc[i][q * 4 + 0]);
                    acc[i][q * 4 + 1] = fmaf(a[i], bb[q].y, acc[i][q * 4 + 1]);
                    acc[i][q * 4 + 2] = fmaf(a[i], bb[q].z, acc[i][q * 4 + 2]);
                    acc[i][q * 4 + 3] = fmaf(a[i], bb[q].w, acc[i][q * 4 + 3]);
                }
            }
        }
        __syncthreads();
    }
#pragma unroll
    for (int q = 0; q < 4; q++) {
        const int n0 = tn * 4 + q * 64;
#pragma unroll
        for (int i = 0; i < 8; i++)
            *(float4*)&sAX[(rm + i) * 260 + n0] =
                make_float4(acc[i][q * 4 + 0], acc[i][q * 4 + 1], acc[i][q * 4 + 2], acc[i][q * 4 + 3]);
    }
    __syncthreads();

    // ================= Phase 4: out = LN( relu(ax @ Wc^T + bc) + x ) ================
#pragma unroll
    for (int i = 0; i < 8; i++)
#pragma unroll
        for (int j = 0; j < 16; j++) acc[i][j] = 0.f;

    for (int kt = 0; kt < CC; kt += 16) {
        { // stage Wc rows transposed: sBt[kk][n] = Wc[n][kt+kk]
            const float* wp = g_Wc + tid * CC + kt;
            float4 w0 = *(const float4*)wp;
            float4 w1 = *(const float4*)(wp + 4);
            float4 w2 = *(const float4*)(wp + 8);
            float4 w3 = *(const float4*)(wp + 12);
            float wv[16] = {w0.x, w0.y, w0.z, w0.w, w1.x, w1.y, w1.z, w1.w,
                            w2.x, w2.y, w2.z, w2.w, w3.x, w3.y, w3.z, w3.w};
#pragma unroll
            for (int kk = 0; kk < 16; kk++) sBt[kk * 260 + tid] = wv[kk];
        }
        __syncthreads();
#pragma unroll 4
        for (int kk = 0; kk < 16; kk++) {
            float a[8];
#pragma unroll
            for (int i = 0; i < 8; i++) a[i] = sAX[(rm + i) * 260 + kt + kk];
            float4 bb[4];
#pragma unroll
            for (int q = 0; q < 4; q++) bb[q] = *(const float4*)&sBt[kk * 260 + tn * 4 + q * 64];
#pragma unroll
            for (int i = 0; i < 8; i++) {
#pragma unroll
                for (int q = 0; q < 4; q++) {
                    acc[i][q * 4 + 0] = fmaf(a[i], bb[q].x, acc[i][q * 4 + 0]);
                    acc[i][q * 4 + 1] = fmaf(a[i], bb[q].y, acc[i][q * 4 + 1]);
                    acc[i][q * 4 + 2] = fmaf(a[i], bb[q].z, acc[i][q * 4 + 2]);
                    acc[i][q * 4 + 3] = fmaf(a[i], bb[q].w, acc[i][q * 4 + 3]);
                }
            }
        }
        __syncthreads();
    }
    // epilogue: bias, relu, residual, LayerNorm
    float hs[8], s2[8];
#pragma unroll
    for (int i = 0; i < 8; i++) { hs[i] = 0.f; s2[i] = 0.f; }
#pragma unroll
    for (int q = 0; q < 4; q++) {
        const int n0 = tn * 4 + q * 64;
        float4 bc4 = *(const float4*)&g_bc[n0];
#pragma unroll
        for (int i = 0; i < 8; i++) {
            float4 xv = __ldg((const float4*)&xb[(rm + i) * CC + n0]);
            float h0 = fmaxf(acc[i][q * 4 + 0] + bc4.x, 0.f) + xv.x;
            float h1 = fmaxf(acc[i][q * 4 + 1] + bc4.y, 0.f) + xv.y;
            float h2 = fmaxf(acc[i][q * 4 + 2] + bc4.z, 0.f) + xv.z;
            float h3 = fmaxf(acc[i][q * 4 + 3] + bc4.w, 0.f) + xv.w;
            acc[i][q * 4 + 0] = h0; acc[i][q * 4 + 1] = h1;
            acc[i][q * 4 + 2] = h2; acc[i][q * 4 + 3] = h3;
            hs[i] += (h0 + h1) + (h2 + h3);
            s2[i] += (h0 * h0 + h1 * h1) + (h2 * h2 + h3 * h3);
        }
    }
#pragma unroll
    for (int i = 0; i < 8; i++) {
        float S = hs[i], Q2 = s2[i];
#pragma unroll
        for (int off = 8; off; off >>= 1) {
            S  += __shfl_xor_sync(0xffffffffu, S, off);
            Q2 += __shfl_xor_sync(0xffffffffu, Q2, off);
        }
        const float mean = S * (1.f / 256.f);
        const float var = Q2 * (1.f / 256.f) - mean * mean;
        hs[i] = mean;
        s2[i] = rsqrtf(var + 1e-5f);
    }
    float* ob = out + (size_t)b * (NF * CC);
#pragma unroll
    for (int q = 0; q < 4; q++) {
        const int n0 = tn * 4 + q * 64;
        float4 g4 = __ldg((const float4*)&gamma[n0]);
        float4 b4 = __ldg((const float4*)&beta[n0]);
#pragma unroll
        for (int i = 0; i < 8; i++) {
            const float m = hs[i], r = s2[i];
            float4 o;
            o.x = (acc[i][q * 4 + 0] - m) * r * g4.x + b4.x;
            o.y = (acc[i][q * 4 + 1] - m) * r * g4.y + b4.y;
            o.z = (acc[i][q * 4 + 2] - m) * r * g4.z + b4.z;
            o.w = (acc[i][q * 4 + 3] - m) * r * g4.w + b4.w;
            *(float4*)&ob[(rm + i) * CC + n0] = o;
        }
    }
}

extern "C" void kernel_launch(void* const* d_in, const int* in_sizes, int n_in,
                              void* d_out, int out_size)
{
    (void)in_sizes; (void)n_in; (void)out_size;
    const float* x     = (const float*)d_in[0];
    const float* ee    = (const float*)d_in[1];
    const float* adj   = (const float*)d_in[2];
    const float* alpha = (const float*)d_in[3];
    const float* Wq    = (const float*)d_in[4];
    const float* bq    = (const float*)d_in[5];
    const float* Wk    = (const float*)d_in[6];
    const float* bk    = (const float*)d_in[7];
    const float* Wv    = (const float*)d_in[8];
    const float* bv    = (const float*)d_in[9];
    const float* Wg    = (const float*)d_in[10];
    const float* bg    = (const float*)d_in[11];
    const float* gamma = (const float*)d_in[12];
    const float* beta  = (const float*)d_in[13];
    float* out = (float*)d_out;

    cudaFuncSetAttribute(fused_kernel, cudaFuncAttributeMaxDynamicSharedMemorySize,
                         SMEM_FLOATS * (int)sizeof(float));
    prep_kernel<<<CC, 256>>>(Wg, Wv, bv, bg);
    fused_kernel<<<BT, 256, SMEM_FLOATS * sizeof(float)>>>(
        x, ee, adj, alpha, Wq, bq, Wk, bk, gamma, beta, out);
}